// round 8
// baseline (speedup 1.0000x reference)
#include <cuda_runtime.h>
#include <cuda_fp16.h>
#include <cstdint>

// ---------------- problem constants ----------------
#define S_   512
#define B_   64
#define T_   768
#define A_   512
#define H1_  768
#define H2_  640
#define M_   (S_*B_)     // 32768
#define NTOT 1408        // H1+H2 = 11 * 128

// ---------------- GEMM tiling ----------------
#define BM   256
#define BN   128
#define BK   64
#define NKS  (T_/BK)     // 12 K-stages
#define STG  3           // pipeline stages (144KB smem, 1 CTA x 512thr / SM)
#define A_STAGE 32768    // 256 x 64 fp16
#define B_STAGE 16384    // 64 x 128 fp16
#define STAGE_BYTES (A_STAGE + B_STAGE)
#define SMEM_DYN (STG*STAGE_BYTES)   // 144 KB

#define KSPL 16          // precompute_c split-K factor
#define SSPLIT 4         // weighted_sum split-S factor

// mega-kernel block ranges
#define PRE_BLOCKS  (11*KSPL)                       // 176
#define CVTB_BLOCKS (T_*NTOT/4/256)                 // 1056
#define CVTA_BLOCKS ((int)((size_t)M_*T_/4/256))    // 24576
#define MEGA_BLOCKS (PRE_BLOCKS + CVTB_BLOCKS + CVTA_BLOCKS)

// ---------------- device scratch (allocation-free rule) ----------------
__device__ __align__(16) __half g_Ah[(size_t)M_*T_];   // text_seq fp16 [m][k]
__device__ __align__(16) __half g_Bh[(size_t)T_*NTOT]; // W11|W12 fp16  [k][n]
__device__ float g_c [B_*NTOT];    // per-batch bias [b][n]
__device__ float g_W2[NTOT];       // W21|W22
__device__ float g_s [2*M_];       // pre-softmax scores [seg][b][s]
__device__ float g_w [M_];         // combined softmax weights [b][s]

// ---------------- helpers ----------------
__device__ __forceinline__ uint32_t s2u(const void* p) {
    return (uint32_t)__cvta_generic_to_shared(p);
}
// A tile: rows of 128B -> XOR bits[6:4] with bits[9:7]
#define SWZA(o) ((o) ^ (((o) >> 3) & 0x70))
// B tile: rows of 256B -> XOR bits[6:4] with bits[10:8]
#define SWZB(o) ((o) ^ ((((o) >> 8) & 7) << 4))

__device__ __forceinline__ void cp16(uint32_t d, const void* s) {
    asm volatile("cp.async.cg.shared.global [%0], [%1], 16;" :: "r"(d), "l"(s) : "memory");
}
#define CP_COMMIT() asm volatile("cp.async.commit_group;" ::: "memory")
#define CP_WAIT1()  asm volatile("cp.async.wait_group 1;" ::: "memory")

#define LDSM_X4(R, addr) \
    asm volatile("ldmatrix.sync.aligned.m8n8.x4.shared.b16 {%0,%1,%2,%3}, [%4];" \
        : "=r"((R)[0]), "=r"((R)[1]), "=r"((R)[2]), "=r"((R)[3]) : "r"(addr))

#define LDSM_X4T(R0, R1, R2, R3, addr) \
    asm volatile("ldmatrix.sync.aligned.m8n8.x4.trans.shared.b16 {%0,%1,%2,%3}, [%4];" \
        : "=r"(R0), "=r"(R1), "=r"(R2), "=r"(R3) : "r"(addr))

#define MMA16816(C, Af, Bf) \
    asm volatile("mma.sync.aligned.m16n8k16.row.col.f32.f16.f16.f32 " \
        "{%0,%1,%2,%3}, {%4,%5,%6,%7}, {%8,%9}, {%0,%1,%2,%3};" \
        : "+f"((C)[0]), "+f"((C)[1]), "+f"((C)[2]), "+f"((C)[3]) \
        : "r"((Af)[0]), "r"((Af)[1]), "r"((Af)[2]), "r"((Af)[3]), \
          "r"((Bf)[0]), "r"((Bf)[1]))

// ---------------------------------------------------------------------------
// init: zero g_s and d_out; seed g_c with the bias vectors; build combined W2
__global__ void init_misc_kernel(const float* __restrict__ b11,
                                 const float* __restrict__ b12,
                                 const float* __restrict__ W21,
                                 const float* __restrict__ W22,
                                 float* __restrict__ out) {
    int i = blockIdx.x * blockDim.x + threadIdx.x;   // < B_*NTOT = 90112
    if (i < 2*M_)  g_s[i] = 0.f;
    if (i < B_*T_) out[i] = 0.f;
    if (i < NTOT)  g_W2[i] = (i < H1_) ? W21[i] : W22[i - H1_];
    int n = i % NTOT;   // seed bias: g_c[b][n] = b11[n] | b12[n-768]
    g_c[i] = (n < H1_) ? b11[n] : b12[n - H1_];
}

// ---------------------------------------------------------------------------
// Mega-kernel: [0,176) precompute_c partials, [176,1232) convert B,
//              [1232, ...) convert A. Compute-bound precompute overlaps the
//              memory-bound converts inside one launch.
__global__ __launch_bounds__(256)
void mega_prep_kernel(const float* __restrict__ text,
                      const float* __restrict__ anp,
                      const float* __restrict__ ts,
                      const float* __restrict__ W11,
                      const float* __restrict__ W12) {
    __shared__ float Wsm[48*128];   // 24KB (max kc=48)
    __shared__ float Xsm[64*48];    // 12KB
    const int bid = blockIdx.x;
    const int tid = threadIdx.x;

    if (bid < PRE_BLOCKS) {
        // ---- precompute_c: g_c[b][n] += sum_k X[b][k] * Wlower[k][n] ----
        const int nc = bid / KSPL, ky = bid % KSPL;
        const int n0 = nc * 128;
        const bool sg0 = (nc < 6);
        const int K   = sg0 ? T_ : A_;
        const int kc  = K / KSPL;                  // 48 or 32
        const int k0  = ky * kc;
        const int wst = sg0 ? H1_ : H2_;
        const float* Wrow = sg0 ? (W11 + (size_t)(T_ + k0)*H1_ + n0)
                                : (W12 + (size_t)(T_ + k0)*H2_ + (n0 - H1_));
        const float* X   = sg0 ? text : anp;
        const int xst    = sg0 ? T_ : A_;

        for (int i = tid; i < kc*128; i += 256) {
            int k = i >> 7, n = i & 127;
            Wsm[i] = Wrow[(size_t)k*wst + n];
        }
        for (int i = tid; i < 64*kc; i += 256) {
            int b = i / kc, k = i - b*kc;
            Xsm[b*kc + k] = X[b*xst + k0 + k];
        }
        __syncthreads();

        const int ng = tid & 15, bq = tid >> 4;
        float acc[4][8];
        #pragma unroll
        for (int j = 0; j < 4; j++)
            #pragma unroll
            for (int i = 0; i < 8; i++) acc[j][i] = 0.f;

        for (int k = 0; k < kc; k++) {
            float4 wa = *(const float4*)&Wsm[k*128 + ng*8];
            float4 wb = *(const float4*)&Wsm[k*128 + ng*8 + 4];
            #pragma unroll
            for (int j = 0; j < 4; j++) {
                float x = Xsm[(bq*4 + j)*kc + k];
                acc[j][0] = fmaf(x, wa.x, acc[j][0]);
                acc[j][1] = fmaf(x, wa.y, acc[j][1]);
                acc[j][2] = fmaf(x, wa.z, acc[j][2]);
                acc[j][3] = fmaf(x, wa.w, acc[j][3]);
                acc[j][4] = fmaf(x, wb.x, acc[j][4]);
                acc[j][5] = fmaf(x, wb.y, acc[j][5]);
                acc[j][6] = fmaf(x, wb.z, acc[j][6]);
                acc[j][7] = fmaf(x, wb.w, acc[j][7]);
            }
        }
        #pragma unroll
        for (int j = 0; j < 4; j++)
            #pragma unroll
            for (int i = 0; i < 8; i++)
                atomicAdd(&g_c[(size_t)(bq*4 + j)*NTOT + n0 + ng*8 + i], acc[j][i]);
    } else if (bid < PRE_BLOCKS + CVTB_BLOCKS) {
        // ---- convert B: g_Bh[k][n] = fp16(W11|W12) ----
        int i = (bid - PRE_BLOCKS)*256 + tid;       // < T_*NTOT/4 exactly
        int k  = i / (NTOT/4);
        int n4 = (i % (NTOT/4)) * 4;
        float4 v;
        if (n4 < H1_) v = *(const float4*)(W11 + (size_t)k*H1_ + n4);
        else          v = *(const float4*)(W12 + (size_t)k*H2_ + (n4 - H1_));
        union { __half2 h[2]; uint2 u; } t;
        t.h[0] = __floats2half2_rn(v.x, v.y);
        t.h[1] = __floats2half2_rn(v.z, v.w);
        ((uint2*)g_Bh)[i] = t.u;
    } else {
        // ---- convert A: text_seq fp32 -> fp16 ----
        size_t i = (size_t)(bid - PRE_BLOCKS - CVTB_BLOCKS)*256 + tid;
        float4 v = ((const float4*)ts)[i];
        union { __half2 h[2]; uint2 u; } t;
        t.h[0] = __floats2half2_rn(v.x, v.y);
        t.h[1] = __floats2half2_rn(v.z, v.w);
        ((uint2*)g_Ah)[i] = t.u;
    }
}

// ---------------------------------------------------------------------------
// Fused fp16 mma.sync GEMM + bias + tanh + W2-dot + score accumulation.
// CTA tile 256(M) x 128(N) x 768(K); 512 threads, 16 warps as 8(M) x 2(N),
// warp tile 32x64. BM=256 halves B-operand L2 traffic vs BM=128.
__global__ __launch_bounds__(512, 1)
void fused_score_mma() {
    extern __shared__ __align__(1024) char smem[];
    const uint32_t sb = s2u(smem);
    const int tid  = threadIdx.x;
    const int lane = tid & 31;
    const int wid  = tid >> 5;
    const int warp_m = wid & 7;    // 0..7  -> m offset 32*warp_m
    const int warp_n = wid >> 3;   // 0..1  -> n offset 64*warp_n

    const int n0 = blockIdx.x * BN;   // x fastest: N tiles share A panel via L2
    const int m0 = blockIdx.y * BM;
    const int seg = (n0 >= H1_) ? 1 : 0;

    float cr[2][8][4];
    #pragma unroll
    for (int mi = 0; mi < 2; mi++)
        #pragma unroll
        for (int ni = 0; ni < 8; ni++)
            #pragma unroll
            for (int r = 0; r < 4; r++) cr[mi][ni][r] = 0.f;

    auto load_stage = [&](int buf, int ks) {
        const uint32_t sA = sb + buf*STAGE_BYTES;
        const uint32_t sB = sA + A_STAGE;
        #pragma unroll
        for (int j = 0; j < 4; j++) {               // A: 256x64 fp16 = 2048 cp16
            int i = tid + 512*j;
            int row = i >> 3, c8 = i & 7;
            cp16(sA + SWZA(row*128 + c8*16),
                 g_Ah + (size_t)(m0 + row)*T_ + ks*BK + c8*8);
        }
        #pragma unroll
        for (int j = 0; j < 2; j++) {               // B: 64x128 fp16 = 1024 cp16
            int i = tid + 512*j;
            int k = i >> 4, n16 = i & 15;
            cp16(sB + SWZB(k*256 + n16*16),
                 g_Bh + (size_t)(ks*BK + k)*NTOT + n0 + n16*8);
        }
    };

    auto compute_stage = [&](int buf) {
        const uint32_t sA = sb + buf*STAGE_BYTES;
        const uint32_t sB = sA + A_STAGE;
        #pragma unroll
        for (int kk = 0; kk < 4; kk++) {            // four k16 steps
            uint32_t af[2][4];
            #pragma unroll
            for (int mi = 0; mi < 2; mi++) {
                int m_l = warp_m*32 + mi*16 + (lane & 15);
                int kc  = kk*16 + (lane >> 4)*8;
                LDSM_X4(af[mi], sA + SWZA(m_l*128 + kc*2));
            }
            uint32_t bf[8][2];
            #pragma unroll
            for (int nj = 0; nj < 4; nj++) {
                int k = kk*16 + ((lane >> 3) & 1)*8 + (lane & 7);
                int n = warp_n*64 + nj*16 + (lane >> 4)*8;
                uint32_t r0, r1, r2, r3;
                LDSM_X4T(r0, r1, r2, r3, sB + SWZB(k*256 + n*2));
                bf[nj*2  ][0] = r0; bf[nj*2  ][1] = r1;
                bf[nj*2+1][0] = r2; bf[nj*2+1][1] = r3;
            }
            #pragma unroll
            for (int mi = 0; mi < 2; mi++)
                #pragma unroll
                for (int ni = 0; ni < 8; ni++)
                    MMA16816(cr[mi][ni], af[mi], bf[ni]);
        }
    };

    // prologue: stages 0..1
    #pragma unroll
    for (int s = 0; s < STG-1; s++) { load_stage(s, s); CP_COMMIT(); }

    #pragma unroll 1
    for (int ks = 0; ks < NKS; ks++) {
        CP_WAIT1();
        __syncthreads();
        int ld = ks + STG - 1;
        if (ld < NKS) load_stage(ld % STG, ld);
        CP_COMMIT();
        compute_stage(ks % STG);
    }

    // ---- epilogue: stage bias tile + W2 in smem (reuse pipeline smem) ----
    __syncthreads();
    float* c_s  = (float*)smem;            // [64][128] = 32KB
    float* w2_s = c_s + 64*128;
    for (int i = tid; i < 64*128; i += 512) {
        int b = i >> 7, n = i & 127;
        c_s[i] = g_c[(size_t)b*NTOT + n0 + n];
    }
    if (tid < 128) w2_s[tid] = g_W2[n0 + tid];
    __syncthreads();

    float p[4];
    #pragma unroll
    for (int mi = 0; mi < 2; mi++) {
        #pragma unroll
        for (int hf = 0; hf < 2; hf++) {
            int r  = warp_m*32 + mi*16 + hf*8 + (lane >> 2);
            int bb = r & 63;                       // m0 multiple of 256, B=64
            const float* crow = c_s + bb*128;
            float acc = 0.f;
            #pragma unroll
            for (int ni = 0; ni < 8; ni++) {
                int cc = warp_n*64 + ni*8 + (lane & 3)*2;
                float u0 = cr[mi][ni][hf*2+0] + crow[cc];
                float u1 = cr[mi][ni][hf*2+1] + crow[cc+1];
                acc += tanhf(u0)*w2_s[cc] + tanhf(u1)*w2_s[cc+1];
            }
            p[mi*2 + hf] = acc;
        }
    }
    #pragma unroll
    for (int i = 0; i < 4; i++) {
        p[i] += __shfl_xor_sync(0xffffffffu, p[i], 1);
        p[i] += __shfl_xor_sync(0xffffffffu, p[i], 2);
    }
    if ((lane & 3) == 0) {
        #pragma unroll
        for (int mi = 0; mi < 2; mi++)
            #pragma unroll
            for (int hf = 0; hf < 2; hf++) {
                int m = m0 + warp_m*32 + mi*16 + hf*8 + (lane >> 2);
                // transposed score layout: [seg][b][s]
                atomicAdd(&g_s[seg*M_ + (m & 63)*S_ + (m >> 6)], p[mi*2 + hf]);
            }
    }
}

// ---------------------------------------------------------------------------
// softmax over S per batch for both branches (warp-shuffle two-level reduce)
__global__ void softmax_combine_kernel() {
    __shared__ float sred[2][16];
    const int b = blockIdx.x;
    const int s = threadIdx.x;      // 512
    const int lane = s & 31, wrp = s >> 5;

    float v1 = g_s[b*S_ + s];
    float v2 = g_s[M_ + b*S_ + s];

    float m1 = v1, m2 = v2;
    #pragma unroll
    for (int o = 16; o > 0; o >>= 1) {
        m1 = fmaxf(m1, __shfl_xor_sync(0xffffffffu, m1, o));
        m2 = fmaxf(m2, __shfl_xor_sync(0xffffffffu, m2, o));
    }
    if (lane == 0) { sred[0][wrp] = m1; sred[1][wrp] = m2; }
    __syncthreads();
    if (s < 32) {
        float a = sred[0][lane & 15], c = sred[1][lane & 15];
        #pragma unroll
        for (int o = 8; o > 0; o >>= 1) {
            a = fmaxf(a, __shfl_xor_sync(0xffffffffu, a, o));
            c = fmaxf(c, __shfl_xor_sync(0xffffffffu, c, o));
        }
        if (lane == 0) { sred[0][0] = a; sred[1][0] = c; }
    }
    __syncthreads();
    m1 = sred[0][0]; m2 = sred[1][0];
    __syncthreads();

    float e1 = expf(v1 - m1), e2 = expf(v2 - m2);
    float s1 = e1, s2 = e2;
    #pragma unroll
    for (int o = 16; o > 0; o >>= 1) {
        s1 += __shfl_xor_sync(0xffffffffu, s1, o);
        s2 += __shfl_xor_sync(0xffffffffu, s2, o);
    }
    if (lane == 0) { sred[0][wrp] = s1; sred[1][wrp] = s2; }
    __syncthreads();
    if (s < 32) {
        float a = sred[0][lane & 15], c = sred[1][lane & 15];
        #pragma unroll
        for (int o = 8; o > 0; o >>= 1) {
            a += __shfl_xor_sync(0xffffffffu, a, o);
            c += __shfl_xor_sync(0xffffffffu, c, o);
        }
        if (lane == 0) { sred[0][0] = a; sred[1][0] = c; }
    }
    __syncthreads();
    s1 = sred[0][0]; s2 = sred[1][0];

    g_w[b*S_ + s] = (e1/s1 + e2/s2) * (0.5f / (float)S_);
}

// ---------------------------------------------------------------------------
// out[b,t] += sum_{s in chunk} g_w[b][s] * text_seq[s,b,t]   (split-S x4)
__global__ void weighted_sum_kernel(const float* __restrict__ ts,
                                    float* __restrict__ out) {
    __shared__ float ws[S_/SSPLIT];
    const int b  = blockIdx.y;
    const int sz = blockIdx.z;
    const int sbeg = sz * (S_/SSPLIT);
    const int t = blockIdx.x * blockDim.x + threadIdx.x;
    for (int i = threadIdx.x; i < S_/SSPLIT; i += blockDim.x)
        ws[i] = g_w[b*S_ + sbeg + i];
    __syncthreads();
    float acc = 0.f;
    const float* p = ts + (size_t)sbeg * B_ * T_ + (size_t)b * T_ + t;
    #pragma unroll 8
    for (int s = 0; s < S_/SSPLIT; s++)
        acc = fmaf(ws[s], p[(size_t)s * B_ * T_], acc);
    atomicAdd(&out[b*T_ + t], acc);
}

// ---------------------------------------------------------------------------
extern "C" void kernel_launch(void* const* d_in, const int* in_sizes, int n_in,
                              void* d_out, int out_size) {
    const float* text = (const float*)d_in[0];
    const float* anp  = (const float*)d_in[1];
    const float* ts   = (const float*)d_in[2];
    const float* W11  = (const float*)d_in[3];
    const float* b11  = (const float*)d_in[4];
    const float* W21  = (const float*)d_in[5];
    // d_in[6] = b21 (softmax shift-invariant -> unused)
    const float* W12  = (const float*)d_in[7];
    const float* b12  = (const float*)d_in[8];
    const float* W22  = (const float*)d_in[9];
    // d_in[10] = b22 (unused)
    (void)in_sizes; (void)n_in; (void)out_size;

    cudaFuncSetAttribute(fused_score_mma,
                         cudaFuncAttributeMaxDynamicSharedMemorySize, SMEM_DYN);

    init_misc_kernel<<<B_*NTOT/256, 256>>>(b11, b12, W21, W22, (float*)d_out);

    mega_prep_kernel<<<MEGA_BLOCKS, 256>>>(text, anp, ts, W11, W12);

    dim3 g1(NTOT/BN, M_/BM);   // (11, 128), N-tiles fastest -> A reuse in L2
    fused_score_mma<<<g1, 512, SMEM_DYN>>>();

    softmax_combine_kernel<<<B_, S_>>>();

    dim3 g2(T_/256, B_, SSPLIT);
    weighted_sum_kernel<<<g2, 256>>>(ts, (float*)d_out);
}

// round 10
// speedup vs baseline: 1.2263x; 1.2263x over previous
#include <cuda_runtime.h>
#include <cuda_fp16.h>
#include <cstdint>

// ---------------- problem constants ----------------
#define S_   512
#define B_   64
#define T_   768
#define A_   512
#define H1_  768
#define H2_  640
#define M_   (S_*B_)     // 32768
#define NTOT 1408        // H1+H2 = 11 * 128

// ---------------- GEMM tiling ----------------
#define BM   128
#define BN   128
#define BK   64
#define NKS  (T_/BK)     // 12 K-stages
#define STG  3           // pipeline stages (96KB smem -> 2 CTAs/SM)
#define A_STAGE 16384    // 128 x 64 fp16
#define B_STAGE 16384    // 64 x 128 fp16
#define STAGE_BYTES (A_STAGE + B_STAGE)
#define SMEM_DYN (STG*STAGE_BYTES)   // 96 KB

#define KSPL 16          // precompute_c split-K factor
#define SSPLIT 4         // weighted_sum split-S factor

// mega-kernel block ranges
#define PRE_BLOCKS  (11*KSPL)                       // 176
#define CVTB_BLOCKS (T_*NTOT/4/256)                 // 1056
#define CVTA_BLOCKS ((int)((size_t)M_*T_/4/256))    // 24576
#define MEGA_BLOCKS (PRE_BLOCKS + CVTB_BLOCKS + CVTA_BLOCKS)

// ---------------- device scratch (allocation-free rule) ----------------
__device__ __align__(16) __half g_Ah[(size_t)M_*T_];   // text_seq fp16 [m][k]
__device__ __align__(16) __half g_Bh[(size_t)T_*NTOT]; // W11|W12 fp16  [k][n]
__device__ __align__(16) float g_c [B_*NTOT];  // per-batch bias [b][n]
__device__ __align__(16) float g_W2[NTOT];     // W21|W22
__device__ float g_s [2*M_];       // pre-softmax scores [seg][b][s]
__device__ float g_w [M_];         // combined softmax weights [b][s]

// ---------------- helpers ----------------
__device__ __forceinline__ uint32_t s2u(const void* p) {
    return (uint32_t)__cvta_generic_to_shared(p);
}
// A tile: rows of 128B -> XOR bits[6:4] with bits[9:7]
#define SWZA(o) ((o) ^ (((o) >> 3) & 0x70))
// B tile: rows of 256B -> XOR bits[6:4] with bits[10:8]
#define SWZB(o) ((o) ^ ((((o) >> 8) & 7) << 4))

__device__ __forceinline__ void cp16(uint32_t d, const void* s) {
    asm volatile("cp.async.cg.shared.global [%0], [%1], 16;" :: "r"(d), "l"(s) : "memory");
}
#define CP_COMMIT() asm volatile("cp.async.commit_group;" ::: "memory")
#define CP_WAIT1()  asm volatile("cp.async.wait_group 1;" ::: "memory")
#define CP_WAIT0()  asm volatile("cp.async.wait_group 0;" ::: "memory")

#define LDSM_X4(R, addr) \
    asm volatile("ldmatrix.sync.aligned.m8n8.x4.shared.b16 {%0,%1,%2,%3}, [%4];" \
        : "=r"((R)[0]), "=r"((R)[1]), "=r"((R)[2]), "=r"((R)[3]) : "r"(addr))

#define LDSM_X4T(R0, R1, R2, R3, addr) \
    asm volatile("ldmatrix.sync.aligned.m8n8.x4.trans.shared.b16 {%0,%1,%2,%3}, [%4];" \
        : "=r"(R0), "=r"(R1), "=r"(R2), "=r"(R3) : "r"(addr))

#define MMA16816(C, Af, Bf) \
    asm volatile("mma.sync.aligned.m16n8k16.row.col.f32.f16.f16.f32 " \
        "{%0,%1,%2,%3}, {%4,%5,%6,%7}, {%8,%9}, {%0,%1,%2,%3};" \
        : "+f"((C)[0]), "+f"((C)[1]), "+f"((C)[2]), "+f"((C)[3]) \
        : "r"((Af)[0]), "r"((Af)[1]), "r"((Af)[2]), "r"((Af)[3]), \
          "r"((Bf)[0]), "r"((Bf)[1]))

// ---------------------------------------------------------------------------
// init: zero g_s and d_out; seed g_c with the bias vectors; build combined W2
__global__ void init_misc_kernel(const float* __restrict__ b11,
                                 const float* __restrict__ b12,
                                 const float* __restrict__ W21,
                                 const float* __restrict__ W22,
                                 float* __restrict__ out) {
    int i = blockIdx.x * blockDim.x + threadIdx.x;   // < B_*NTOT = 90112
    if (i < 2*M_)  g_s[i] = 0.f;
    if (i < B_*T_) out[i] = 0.f;
    if (i < NTOT)  g_W2[i] = (i < H1_) ? W21[i] : W22[i - H1_];
    int n = i % NTOT;   // seed bias: g_c[b][n] = b11[n] | b12[n-768]
    g_c[i] = (n < H1_) ? b11[n] : b12[n - H1_];
}

// ---------------------------------------------------------------------------
// Mega-kernel: [0,176) precompute_c partials, [176,1232) convert B,
//              [1232, ...) convert A.
__global__ __launch_bounds__(256)
void mega_prep_kernel(const float* __restrict__ text,
                      const float* __restrict__ anp,
                      const float* __restrict__ ts,
                      const float* __restrict__ W11,
                      const float* __restrict__ W12) {
    __shared__ float Wsm[48*128];   // 24KB (max kc=48)
    __shared__ float Xsm[64*48];    // 12KB
    const int bid = blockIdx.x;
    const int tid = threadIdx.x;

    if (bid < PRE_BLOCKS) {
        // ---- precompute_c: g_c[b][n] += sum_k X[b][k] * Wlower[k][n] ----
        const int nc = bid / KSPL, ky = bid % KSPL;
        const int n0 = nc * 128;
        const bool sg0 = (nc < 6);
        const int K   = sg0 ? T_ : A_;
        const int kc  = K / KSPL;                  // 48 or 32
        const int k0  = ky * kc;
        const int wst = sg0 ? H1_ : H2_;
        const float* Wrow = sg0 ? (W11 + (size_t)(T_ + k0)*H1_ + n0)
                                : (W12 + (size_t)(T_ + k0)*H2_ + (n0 - H1_));
        const float* X   = sg0 ? text : anp;
        const int xst    = sg0 ? T_ : A_;

        for (int i = tid; i < kc*128; i += 256) {
            int k = i >> 7, n = i & 127;
            Wsm[i] = Wrow[(size_t)k*wst + n];
        }
        for (int i = tid; i < 64*kc; i += 256) {
            int b = i / kc, k = i - b*kc;
            Xsm[b*kc + k] = X[b*xst + k0 + k];
        }
        __syncthreads();

        const int ng = tid & 15, bq = tid >> 4;
        float acc[4][8];
        #pragma unroll
        for (int j = 0; j < 4; j++)
            #pragma unroll
            for (int i = 0; i < 8; i++) acc[j][i] = 0.f;

        for (int k = 0; k < kc; k++) {
            float4 wa = *(const float4*)&Wsm[k*128 + ng*8];
            float4 wb = *(const float4*)&Wsm[k*128 + ng*8 + 4];
            #pragma unroll
            for (int j = 0; j < 4; j++) {
                float x = Xsm[(bq*4 + j)*kc + k];
                acc[j][0] = fmaf(x, wa.x, acc[j][0]);
                acc[j][1] = fmaf(x, wa.y, acc[j][1]);
                acc[j][2] = fmaf(x, wa.z, acc[j][2]);
                acc[j][3] = fmaf(x, wa.w, acc[j][3]);
                acc[j][4] = fmaf(x, wb.x, acc[j][4]);
                acc[j][5] = fmaf(x, wb.y, acc[j][5]);
                acc[j][6] = fmaf(x, wb.z, acc[j][6]);
                acc[j][7] = fmaf(x, wb.w, acc[j][7]);
            }
        }
        #pragma unroll
        for (int j = 0; j < 4; j++)
            #pragma unroll
            for (int i = 0; i < 8; i++)
                atomicAdd(&g_c[(size_t)(bq*4 + j)*NTOT + n0 + ng*8 + i], acc[j][i]);
    } else if (bid < PRE_BLOCKS + CVTB_BLOCKS) {
        // ---- convert B: g_Bh[k][n] = fp16(W11|W12) ----
        int i = (bid - PRE_BLOCKS)*256 + tid;
        int k  = i / (NTOT/4);
        int n4 = (i % (NTOT/4)) * 4;
        float4 v;
        if (n4 < H1_) v = *(const float4*)(W11 + (size_t)k*H1_ + n4);
        else          v = *(const float4*)(W12 + (size_t)k*H2_ + (n4 - H1_));
        union { __half2 h[2]; uint2 u; } t;
        t.h[0] = __floats2half2_rn(v.x, v.y);
        t.h[1] = __floats2half2_rn(v.z, v.w);
        ((uint2*)g_Bh)[i] = t.u;
    } else {
        // ---- convert A: text_seq fp32 -> fp16 ----
        size_t i = (size_t)(bid - PRE_BLOCKS - CVTB_BLOCKS)*256 + tid;
        float4 v = ((const float4*)ts)[i];
        union { __half2 h[2]; uint2 u; } t;
        t.h[0] = __floats2half2_rn(v.x, v.y);
        t.h[1] = __floats2half2_rn(v.z, v.w);
        ((uint2*)g_Ah)[i] = t.u;
    }
}

// ---------------------------------------------------------------------------
// Fused fp16 mma.sync GEMM + bias + tanh + W2-dot + score accumulation.
// CTA tile 128(M) x 128(N) x 768(K); 8 warps as 4(M) x 2(N), warp tile 32x64.
// 96KB smem, 2 CTAs/SM. Pipeline order: wait -> sync -> load -> compute
// (wait_group MUST precede the publishing barrier for cross-thread visibility).
__global__ __launch_bounds__(256, 2)
void fused_score_mma() {
    extern __shared__ __align__(1024) char smem[];
    const uint32_t sb = s2u(smem);
    const int tid  = threadIdx.x;
    const int lane = tid & 31;
    const int wid  = tid >> 5;
    const int warp_m = wid & 3;    // 0..3  -> m offset 32*warp_m
    const int warp_n = wid >> 2;   // 0..1  -> n offset 64*warp_n

    const int n0 = blockIdx.x * BN;   // x fastest: N tiles share A panel via L2
    const int m0 = blockIdx.y * BM;
    const int seg = (n0 >= H1_) ? 1 : 0;

    float cr[2][8][4];
    #pragma unroll
    for (int mi = 0; mi < 2; mi++)
        #pragma unroll
        for (int ni = 0; ni < 8; ni++)
            #pragma unroll
            for (int r = 0; r < 4; r++) cr[mi][ni][r] = 0.f;

    auto load_stage = [&](int buf, int ks) {
        const uint32_t sA = sb + buf*STAGE_BYTES;
        const uint32_t sB = sA + A_STAGE;
        #pragma unroll
        for (int j = 0; j < 4; j++) {
            int i = tid + 256*j;
            int row = i >> 3, c8 = i & 7;
            cp16(sA + SWZA(row*128 + c8*16),
                 g_Ah + (size_t)(m0 + row)*T_ + ks*BK + c8*8);
        }
        #pragma unroll
        for (int j = 0; j < 4; j++) {
            int i = tid + 256*j;
            int k = i >> 4, n16 = i & 15;
            cp16(sB + SWZB(k*256 + n16*16),
                 g_Bh + (size_t)(ks*BK + k)*NTOT + n0 + n16*8);
        }
    };

    // bias/W2 prefetch into dead buffers 0..1 (WAR-safe after top-of-loop sync;
    // drained by CP_WAIT0 + __syncthreads after the loop)
    auto load_bias = [&]() {
        #pragma unroll
        for (int j = 0; j < 8; j++) {            // c tile: 64x128 f32 = 2048 cp16
            int i = tid + 256*j;
            int b = i >> 5, c4 = i & 31;
            cp16(sb + (uint32_t)i*16, g_c + (size_t)b*NTOT + n0 + c4*4);
        }
        if (tid < 32)                            // W2: 128 f32 = 32 cp16
            cp16(sb + 32768u + (uint32_t)tid*16, g_W2 + n0 + tid*4);
    };

    auto compute_stage = [&](int buf) {
        const uint32_t sA = sb + buf*STAGE_BYTES;
        const uint32_t sB = sA + A_STAGE;
        #pragma unroll
        for (int kk = 0; kk < 4; kk++) {            // four k16 steps
            uint32_t af[2][4];
            #pragma unroll
            for (int mi = 0; mi < 2; mi++) {
                int m_l = warp_m*32 + mi*16 + (lane & 15);
                int kc  = kk*16 + (lane >> 4)*8;
                LDSM_X4(af[mi], sA + SWZA(m_l*128 + kc*2));
            }
            uint32_t bf[8][2];
            #pragma unroll
            for (int nj = 0; nj < 4; nj++) {
                int k = kk*16 + ((lane >> 3) & 1)*8 + (lane & 7);
                int n = warp_n*64 + nj*16 + (lane >> 4)*8;
                uint32_t r0, r1, r2, r3;
                LDSM_X4T(r0, r1, r2, r3, sB + SWZB(k*256 + n*2));
                bf[nj*2  ][0] = r0; bf[nj*2  ][1] = r1;
                bf[nj*2+1][0] = r2; bf[nj*2+1][1] = r3;
            }
            #pragma unroll
            for (int mi = 0; mi < 2; mi++)
                #pragma unroll
                for (int ni = 0; ni < 8; ni++)
                    MMA16816(cr[mi][ni], af[mi], bf[ni]);
        }
    };

    // prologue: stages 0..1
    #pragma unroll
    for (int s = 0; s < STG-1; s++) { load_stage(s, s); CP_COMMIT(); }

    #pragma unroll 1
    for (int ks = 0; ks < NKS; ks++) {
        CP_WAIT1();                      // own groups thru stage ks complete
        __syncthreads();                 // publish cp.async data CTA-wide (+WAR)
        int ld = ks + STG - 1;
        if (ld < NKS)            load_stage(ld % STG, ld);
        else if (ks == NKS - 1)  load_bias();
        CP_COMMIT();
        compute_stage(ks % STG);
    }

    // ---- epilogue: bias tile + W2 streamed into buffers 0/1 ----
    CP_WAIT0();
    __syncthreads();
    const float* c_s  = (const float*)smem;          // [64][128]
    const float* w2_s = (const float*)(smem + 32768);

    float p[4];
    #pragma unroll
    for (int mi = 0; mi < 2; mi++) {
        #pragma unroll
        for (int hf = 0; hf < 2; hf++) {
            int r  = warp_m*32 + mi*16 + hf*8 + (lane >> 2);
            int bb = r & 63;                       // m0 multiple of 128, B=64
            const float* crow = c_s + bb*128;
            float acc = 0.f;
            #pragma unroll
            for (int ni = 0; ni < 8; ni++) {
                int cc = warp_n*64 + ni*8 + (lane & 3)*2;
                float u0 = cr[mi][ni][hf*2+0] + crow[cc];
                float u1 = cr[mi][ni][hf*2+1] + crow[cc+1];
                acc += tanhf(u0)*w2_s[cc] + tanhf(u1)*w2_s[cc+1];
            }
            p[mi*2 + hf] = acc;
        }
    }
    #pragma unroll
    for (int i = 0; i < 4; i++) {
        p[i] += __shfl_xor_sync(0xffffffffu, p[i], 1);
        p[i] += __shfl_xor_sync(0xffffffffu, p[i], 2);
    }
    if ((lane & 3) == 0) {
        #pragma unroll
        for (int mi = 0; mi < 2; mi++)
            #pragma unroll
            for (int hf = 0; hf < 2; hf++) {
                int m = m0 + warp_m*32 + mi*16 + hf*8 + (lane >> 2);
                // transposed score layout: [seg][b][s]
                atomicAdd(&g_s[seg*M_ + (m & 63)*S_ + (m >> 6)], p[mi*2 + hf]);
            }
    }
}

// ---------------------------------------------------------------------------
// softmax over S per batch for both branches (warp-shuffle two-level reduce)
__global__ void softmax_combine_kernel() {
    __shared__ float sred[2][16];
    const int b = blockIdx.x;
    const int s = threadIdx.x;      // 512
    const int lane = s & 31, wrp = s >> 5;

    float v1 = g_s[b*S_ + s];
    float v2 = g_s[M_ + b*S_ + s];

    float m1 = v1, m2 = v2;
    #pragma unroll
    for (int o = 16; o > 0; o >>= 1) {
        m1 = fmaxf(m1, __shfl_xor_sync(0xffffffffu, m1, o));
        m2 = fmaxf(m2, __shfl_xor_sync(0xffffffffu, m2, o));
    }
    if (lane == 0) { sred[0][wrp] = m1; sred[1][wrp] = m2; }
    __syncthreads();
    if (s < 32) {
        float a = sred[0][lane & 15], c = sred[1][lane & 15];
        #pragma unroll
        for (int o = 8; o > 0; o >>= 1) {
            a = fmaxf(a, __shfl_xor_sync(0xffffffffu, a, o));
            c = fmaxf(c, __shfl_xor_sync(0xffffffffu, c, o));
        }
        if (lane == 0) { sred[0][0] = a; sred[1][0] = c; }
    }
    __syncthreads();
    m1 = sred[0][0]; m2 = sred[1][0];
    __syncthreads();

    float e1 = expf(v1 - m1), e2 = expf(v2 - m2);
    float s1 = e1, s2 = e2;
    #pragma unroll
    for (int o = 16; o > 0; o >>= 1) {
        s1 += __shfl_xor_sync(0xffffffffu, s1, o);
        s2 += __shfl_xor_sync(0xffffffffu, s2, o);
    }
    if (lane == 0) { sred[0][wrp] = s1; sred[1][wrp] = s2; }
    __syncthreads();
    if (s < 32) {
        float a = sred[0][lane & 15], c = sred[1][lane & 15];
        #pragma unroll
        for (int o = 8; o > 0; o >>= 1) {
            a += __shfl_xor_sync(0xffffffffu, a, o);
            c += __shfl_xor_sync(0xffffffffu, c, o);
        }
        if (lane == 0) { sred[0][0] = a; sred[1][0] = c; }
    }
    __syncthreads();
    s1 = sred[0][0]; s2 = sred[1][0];

    g_w[b*S_ + s] = (e1/s1 + e2/s2) * (0.5f / (float)S_);
}

// ---------------------------------------------------------------------------
// out[b,t] += sum_{s in chunk} g_w[b][s] * fp16(text_seq)[s,b,t]  (split-S x4)
// reads the fp16 copy: half the DRAM traffic; adds ~2e-4 rel err (gate 1e-3)
__global__ void weighted_sum_kernel(float* __restrict__ out) {
    __shared__ float ws[S_/SSPLIT];
    const int b  = blockIdx.y;
    const int sz = blockIdx.z;
    const int sbeg = sz * (S_/SSPLIT);
    const int t2 = blockIdx.x * blockDim.x + threadIdx.x;   // half2 index
    for (int i = threadIdx.x; i < S_/SSPLIT; i += blockDim.x)
        ws[i] = g_w[b*S_ + sbeg + i];
    __syncthreads();
    float a0 = 0.f, a1 = 0.f;
    const __half2* p = (const __half2*)g_Ah
                     + ((size_t)sbeg * B_ + b) * (T_/2) + t2;
    #pragma unroll 8
    for (int s = 0; s < S_/SSPLIT; s++) {
        float2 x = __half22float2(p[(size_t)s * B_ * (T_/2)]);
        a0 = fmaf(ws[s], x.x, a0);
        a1 = fmaf(ws[s], x.y, a1);
    }
    atomicAdd(&out[b*T_ + t2*2],     a0);
    atomicAdd(&out[b*T_ + t2*2 + 1], a1);
}

// ---------------------------------------------------------------------------
extern "C" void kernel_launch(void* const* d_in, const int* in_sizes, int n_in,
                              void* d_out, int out_size) {
    const float* text = (const float*)d_in[0];
    const float* anp  = (const float*)d_in[1];
    const float* ts   = (const float*)d_in[2];
    const float* W11  = (const float*)d_in[3];
    const float* b11  = (const float*)d_in[4];
    const float* W21  = (const float*)d_in[5];
    // d_in[6] = b21 (softmax shift-invariant -> unused)
    const float* W12  = (const float*)d_in[7];
    const float* b12  = (const float*)d_in[8];
    const float* W22  = (const float*)d_in[9];
    // d_in[10] = b22 (unused)
    (void)in_sizes; (void)n_in; (void)out_size;

    cudaFuncSetAttribute(fused_score_mma,
                         cudaFuncAttributeMaxDynamicSharedMemorySize, SMEM_DYN);

    init_misc_kernel<<<B_*NTOT/256, 256>>>(b11, b12, W21, W22, (float*)d_out);

    mega_prep_kernel<<<MEGA_BLOCKS, 256>>>(text, anp, ts, W11, W12);

    dim3 g1(NTOT/BN, M_/BM);   // (11, 256), N-tiles fastest -> A reuse in L2
    fused_score_mma<<<g1, 256, SMEM_DYN>>>();

    softmax_combine_kernel<<<B_, S_>>>();

    dim3 g2(T_/2/128, B_, SSPLIT);
    weighted_sum_kernel<<<g2, 128>>>((float*)d_out);
}

// round 11
// speedup vs baseline: 1.2654x; 1.0319x over previous
#include <cuda_runtime.h>
#include <cuda_fp16.h>
#include <cstdint>

// ---------------- problem constants ----------------
#define S_   512
#define B_   64
#define T_   768
#define A_   512
#define H1_  768
#define H2_  640
#define M_   (S_*B_)     // 32768
#define NTOT 1408        // H1+H2 = 11 * 128

// ---------------- GEMM tiling ----------------
#define BM   128
#define BN   128
#define BK   64
#define NKS  (T_/BK)     // 12 K-stages
#define STG  3           // pipeline stages (96KB smem -> 2 CTAs/SM)
#define A_STAGE 16384    // 128 x 64 fp16
#define B_STAGE 16384    // 64 x 128 fp16
#define STAGE_BYTES (A_STAGE + B_STAGE)
#define SMEM_DYN (STG*STAGE_BYTES)   // 96 KB

#define KSPL 16          // precompute_c split-K factor
#define SSPLIT 4         // weighted_sum split-S factor

// mega-kernel block ranges
#define PRE_BLOCKS  (11*KSPL)                       // 176
#define CVTB_BLOCKS (T_*NTOT/4/256)                 // 1056
#define CVTA_BLOCKS ((int)((size_t)M_*T_/4/256))    // 24576
#define MEGA_BLOCKS (PRE_BLOCKS + CVTB_BLOCKS + CVTA_BLOCKS)

// ---------------- device scratch (allocation-free rule) ----------------
__device__ __align__(16) __half g_Ah[(size_t)M_*T_];   // text_seq fp16 [m][k]
__device__ __align__(16) __half g_Bh[(size_t)T_*NTOT]; // W11|W12 fp16  [k][n]
__device__ __align__(16) float g_c [B_*NTOT];  // per-batch bias [b][n]
__device__ __align__(16) float g_W2[NTOT];     // W21|W22
__device__ float g_s [2*M_];       // pre-softmax scores [seg][b][s]

// ---------------- helpers ----------------
__device__ __forceinline__ uint32_t s2u(const void* p) {
    return (uint32_t)__cvta_generic_to_shared(p);
}
__device__ __forceinline__ float tanh_fast(float x) {
    float y;
    asm("tanh.approx.f32 %0, %1;" : "=f"(y) : "f"(x));
    return y;
}
// A tile: rows of 128B -> XOR bits[6:4] with bits[9:7]
#define SWZA(o) ((o) ^ (((o) >> 3) & 0x70))
// B tile: rows of 256B -> XOR bits[6:4] with bits[10:8]
#define SWZB(o) ((o) ^ ((((o) >> 8) & 7) << 4))

__device__ __forceinline__ void cp16(uint32_t d, const void* s) {
    asm volatile("cp.async.cg.shared.global [%0], [%1], 16;" :: "r"(d), "l"(s) : "memory");
}
#define CP_COMMIT() asm volatile("cp.async.commit_group;" ::: "memory")
#define CP_WAIT1()  asm volatile("cp.async.wait_group 1;" ::: "memory")
#define CP_WAIT0()  asm volatile("cp.async.wait_group 0;" ::: "memory")

#define LDSM_X4(R, addr) \
    asm volatile("ldmatrix.sync.aligned.m8n8.x4.shared.b16 {%0,%1,%2,%3}, [%4];" \
        : "=r"((R)[0]), "=r"((R)[1]), "=r"((R)[2]), "=r"((R)[3]) : "r"(addr))

#define LDSM_X4T(R0, R1, R2, R3, addr) \
    asm volatile("ldmatrix.sync.aligned.m8n8.x4.trans.shared.b16 {%0,%1,%2,%3}, [%4];" \
        : "=r"(R0), "=r"(R1), "=r"(R2), "=r"(R3) : "r"(addr))

#define MMA16816(C, Af, Bf) \
    asm volatile("mma.sync.aligned.m16n8k16.row.col.f32.f16.f16.f32 " \
        "{%0,%1,%2,%3}, {%4,%5,%6,%7}, {%8,%9}, {%0,%1,%2,%3};" \
        : "+f"((C)[0]), "+f"((C)[1]), "+f"((C)[2]), "+f"((C)[3]) \
        : "r"((Af)[0]), "r"((Af)[1]), "r"((Af)[2]), "r"((Af)[3]), \
          "r"((Bf)[0]), "r"((Bf)[1]))

// ---------------------------------------------------------------------------
// init: zero g_s and d_out; seed g_c with the bias vectors; build combined W2
__global__ void init_misc_kernel(const float* __restrict__ b11,
                                 const float* __restrict__ b12,
                                 const float* __restrict__ W21,
                                 const float* __restrict__ W22,
                                 float* __restrict__ out) {
    int i = blockIdx.x * blockDim.x + threadIdx.x;   // < B_*NTOT = 90112
    if (i < 2*M_)  g_s[i] = 0.f;
    if (i < B_*T_) out[i] = 0.f;
    if (i < NTOT)  g_W2[i] = (i < H1_) ? W21[i] : W22[i - H1_];
    int n = i % NTOT;   // seed bias: g_c[b][n] = b11[n] | b12[n-768]
    g_c[i] = (n < H1_) ? b11[n] : b12[n - H1_];
}

// ---------------------------------------------------------------------------
// Mega-kernel: [0,176) precompute_c partials, [176,1232) convert B,
//              [1232, ...) convert A.
__global__ __launch_bounds__(256)
void mega_prep_kernel(const float* __restrict__ text,
                      const float* __restrict__ anp,
                      const float* __restrict__ ts,
                      const float* __restrict__ W11,
                      const float* __restrict__ W12) {
    __shared__ float Wsm[48*128];   // 24KB (max kc=48)
    __shared__ float Xsm[64*48];    // 12KB
    const int bid = blockIdx.x;
    const int tid = threadIdx.x;

    if (bid < PRE_BLOCKS) {
        // ---- precompute_c: g_c[b][n] += sum_k X[b][k] * Wlower[k][n] ----
        const int nc = bid / KSPL, ky = bid % KSPL;
        const int n0 = nc * 128;
        const bool sg0 = (nc < 6);
        const int K   = sg0 ? T_ : A_;
        const int kc  = K / KSPL;                  // 48 or 32
        const int k0  = ky * kc;
        const int wst = sg0 ? H1_ : H2_;
        const float* Wrow = sg0 ? (W11 + (size_t)(T_ + k0)*H1_ + n0)
                                : (W12 + (size_t)(T_ + k0)*H2_ + (n0 - H1_));
        const float* X   = sg0 ? text : anp;
        const int xst    = sg0 ? T_ : A_;

        for (int i = tid; i < kc*128; i += 256) {
            int k = i >> 7, n = i & 127;
            Wsm[i] = Wrow[(size_t)k*wst + n];
        }
        for (int i = tid; i < 64*kc; i += 256) {
            int b = i / kc, k = i - b*kc;
            Xsm[b*kc + k] = X[b*xst + k0 + k];
        }
        __syncthreads();

        const int ng = tid & 15, bq = tid >> 4;
        float acc[4][8];
        #pragma unroll
        for (int j = 0; j < 4; j++)
            #pragma unroll
            for (int i = 0; i < 8; i++) acc[j][i] = 0.f;

        for (int k = 0; k < kc; k++) {
            float4 wa = *(const float4*)&Wsm[k*128 + ng*8];
            float4 wb = *(const float4*)&Wsm[k*128 + ng*8 + 4];
            #pragma unroll
            for (int j = 0; j < 4; j++) {
                float x = Xsm[(bq*4 + j)*kc + k];
                acc[j][0] = fmaf(x, wa.x, acc[j][0]);
                acc[j][1] = fmaf(x, wa.y, acc[j][1]);
                acc[j][2] = fmaf(x, wa.z, acc[j][2]);
                acc[j][3] = fmaf(x, wa.w, acc[j][3]);
                acc[j][4] = fmaf(x, wb.x, acc[j][4]);
                acc[j][5] = fmaf(x, wb.y, acc[j][5]);
                acc[j][6] = fmaf(x, wb.z, acc[j][6]);
                acc[j][7] = fmaf(x, wb.w, acc[j][7]);
            }
        }
        #pragma unroll
        for (int j = 0; j < 4; j++)
            #pragma unroll
            for (int i = 0; i < 8; i++)
                atomicAdd(&g_c[(size_t)(bq*4 + j)*NTOT + n0 + ng*8 + i], acc[j][i]);
    } else if (bid < PRE_BLOCKS + CVTB_BLOCKS) {
        // ---- convert B: g_Bh[k][n] = fp16(W11|W12) ----
        int i = (bid - PRE_BLOCKS)*256 + tid;
        int k  = i / (NTOT/4);
        int n4 = (i % (NTOT/4)) * 4;
        float4 v;
        if (n4 < H1_) v = *(const float4*)(W11 + (size_t)k*H1_ + n4);
        else          v = *(const float4*)(W12 + (size_t)k*H2_ + (n4 - H1_));
        union { __half2 h[2]; uint2 u; } t;
        t.h[0] = __floats2half2_rn(v.x, v.y);
        t.h[1] = __floats2half2_rn(v.z, v.w);
        ((uint2*)g_Bh)[i] = t.u;
    } else {
        // ---- convert A: text_seq fp32 -> fp16 ----
        size_t i = (size_t)(bid - PRE_BLOCKS - CVTB_BLOCKS)*256 + tid;
        float4 v = ((const float4*)ts)[i];
        union { __half2 h[2]; uint2 u; } t;
        t.h[0] = __floats2half2_rn(v.x, v.y);
        t.h[1] = __floats2half2_rn(v.z, v.w);
        ((uint2*)g_Ah)[i] = t.u;
    }
}

// ---------------------------------------------------------------------------
// Fused fp16 mma.sync GEMM + bias + tanh + W2-dot + score accumulation.
// CTA tile 128(M) x 128(N) x 768(K); 8 warps as 4(M) x 2(N), warp tile 32x64.
// 96KB smem, 2 CTAs/SM. Pipeline order: wait -> sync -> load -> compute
// (wait_group MUST precede the publishing barrier for cross-thread visibility).
__global__ __launch_bounds__(256, 2)
void fused_score_mma() {
    extern __shared__ __align__(1024) char smem[];
    const uint32_t sb = s2u(smem);
    const int tid  = threadIdx.x;
    const int lane = tid & 31;
    const int wid  = tid >> 5;
    const int warp_m = wid & 3;    // 0..3  -> m offset 32*warp_m
    const int warp_n = wid >> 2;   // 0..1  -> n offset 64*warp_n

    const int n0 = blockIdx.x * BN;   // x fastest: N tiles share A panel via L2
    const int m0 = blockIdx.y * BM;
    const int seg = (n0 >= H1_) ? 1 : 0;

    float cr[2][8][4];
    #pragma unroll
    for (int mi = 0; mi < 2; mi++)
        #pragma unroll
        for (int ni = 0; ni < 8; ni++)
            #pragma unroll
            for (int r = 0; r < 4; r++) cr[mi][ni][r] = 0.f;

    auto load_stage = [&](int buf, int ks) {
        const uint32_t sA = sb + buf*STAGE_BYTES;
        const uint32_t sB = sA + A_STAGE;
        #pragma unroll
        for (int j = 0; j < 4; j++) {
            int i = tid + 256*j;
            int row = i >> 3, c8 = i & 7;
            cp16(sA + SWZA(row*128 + c8*16),
                 g_Ah + (size_t)(m0 + row)*T_ + ks*BK + c8*8);
        }
        #pragma unroll
        for (int j = 0; j < 4; j++) {
            int i = tid + 256*j;
            int k = i >> 4, n16 = i & 15;
            cp16(sB + SWZB(k*256 + n16*16),
                 g_Bh + (size_t)(ks*BK + k)*NTOT + n0 + n16*8);
        }
    };

    // bias/W2 prefetch into dead buffers 0..1 (WAR-safe after top-of-loop sync;
    // drained by CP_WAIT0 + __syncthreads after the loop)
    auto load_bias = [&]() {
        #pragma unroll
        for (int j = 0; j < 8; j++) {            // c tile: 64x128 f32 = 2048 cp16
            int i = tid + 256*j;
            int b = i >> 5, c4 = i & 31;
            cp16(sb + (uint32_t)i*16, g_c + (size_t)b*NTOT + n0 + c4*4);
        }
        if (tid < 32)                            // W2: 128 f32 = 32 cp16
            cp16(sb + 32768u + (uint32_t)tid*16, g_W2 + n0 + tid*4);
    };

    auto compute_stage = [&](int buf) {
        const uint32_t sA = sb + buf*STAGE_BYTES;
        const uint32_t sB = sA + A_STAGE;
        #pragma unroll
        for (int kk = 0; kk < 4; kk++) {            // four k16 steps
            uint32_t af[2][4];
            #pragma unroll
            for (int mi = 0; mi < 2; mi++) {
                int m_l = warp_m*32 + mi*16 + (lane & 15);
                int kc  = kk*16 + (lane >> 4)*8;
                LDSM_X4(af[mi], sA + SWZA(m_l*128 + kc*2));
            }
            uint32_t bf[8][2];
            #pragma unroll
            for (int nj = 0; nj < 4; nj++) {
                int k = kk*16 + ((lane >> 3) & 1)*8 + (lane & 7);
                int n = warp_n*64 + nj*16 + (lane >> 4)*8;
                uint32_t r0, r1, r2, r3;
                LDSM_X4T(r0, r1, r2, r3, sB + SWZB(k*256 + n*2));
                bf[nj*2  ][0] = r0; bf[nj*2  ][1] = r1;
                bf[nj*2+1][0] = r2; bf[nj*2+1][1] = r3;
            }
            #pragma unroll
            for (int mi = 0; mi < 2; mi++)
                #pragma unroll
                for (int ni = 0; ni < 8; ni++)
                    MMA16816(cr[mi][ni], af[mi], bf[ni]);
        }
    };

    // prologue: stages 0..1
    #pragma unroll
    for (int s = 0; s < STG-1; s++) { load_stage(s, s); CP_COMMIT(); }

    #pragma unroll 1
    for (int ks = 0; ks < NKS; ks++) {
        CP_WAIT1();                      // own groups thru stage ks complete
        __syncthreads();                 // publish cp.async data CTA-wide (+WAR)
        int ld = ks + STG - 1;
        if (ld < NKS)            load_stage(ld % STG, ld);
        else if (ks == NKS - 1)  load_bias();
        CP_COMMIT();
        compute_stage(ks % STG);
    }

    // ---- epilogue: bias tile + W2 streamed into buffers 0/1 ----
    CP_WAIT0();
    __syncthreads();
    const float* c_s  = (const float*)smem;          // [64][128]
    const float* w2_s = (const float*)(smem + 32768);

    float p[4];
    #pragma unroll
    for (int mi = 0; mi < 2; mi++) {
        #pragma unroll
        for (int hf = 0; hf < 2; hf++) {
            int r  = warp_m*32 + mi*16 + hf*8 + (lane >> 2);
            int bb = r & 63;                       // m0 multiple of 128, B=64
            const float* crow = c_s + bb*128;
            float acc = 0.f;
            #pragma unroll
            for (int ni = 0; ni < 8; ni++) {
                int cc = warp_n*64 + ni*8 + (lane & 3)*2;
                float u0 = cr[mi][ni][hf*2+0] + crow[cc];
                float u1 = cr[mi][ni][hf*2+1] + crow[cc+1];
                acc += tanh_fast(u0)*w2_s[cc] + tanh_fast(u1)*w2_s[cc+1];
            }
            p[mi*2 + hf] = acc;
        }
    }
    #pragma unroll
    for (int i = 0; i < 4; i++) {
        p[i] += __shfl_xor_sync(0xffffffffu, p[i], 1);
        p[i] += __shfl_xor_sync(0xffffffffu, p[i], 2);
    }
    if ((lane & 3) == 0) {
        #pragma unroll
        for (int mi = 0; mi < 2; mi++)
            #pragma unroll
            for (int hf = 0; hf < 2; hf++) {
                int m = m0 + warp_m*32 + mi*16 + hf*8 + (lane >> 2);
                // transposed score layout: [seg][b][s]
                atomicAdd(&g_s[seg*M_ + (m & 63)*S_ + (m >> 6)], p[mi*2 + hf]);
            }
    }
}

// ---------------------------------------------------------------------------
// Fused softmax + weighted sum. grid (T_/2/128, B_, SSPLIT), block 128.
// Each block redundantly reduces the 512-score vectors for its batch b
// (4KB from L2-resident g_s), builds its 128 local weights in smem, then
// accumulates out[b, t-range] over its S-chunk via atomics.
__global__ __launch_bounds__(128)
void softmax_wsum_kernel(float* __restrict__ out) {
    __shared__ float red[2][4];
    __shared__ float ws[S_/SSPLIT];     // 128 weights for this block's s-chunk
    const int b   = blockIdx.y;
    const int sz  = blockIdx.z;
    const int tid = threadIdx.x;        // 128
    const int lane = tid & 31, wrp = tid >> 5;

    // load all 512 scores per branch (4 chunks of 128)
    float v1[4], v2[4];
    #pragma unroll
    for (int i = 0; i < 4; i++) {
        v1[i] = g_s[b*S_ + i*128 + tid];
        v2[i] = g_s[M_ + b*S_ + i*128 + tid];
    }
    // block max per branch
    float m1 = fmaxf(fmaxf(v1[0], v1[1]), fmaxf(v1[2], v1[3]));
    float m2 = fmaxf(fmaxf(v2[0], v2[1]), fmaxf(v2[2], v2[3]));
    #pragma unroll
    for (int o = 16; o > 0; o >>= 1) {
        m1 = fmaxf(m1, __shfl_xor_sync(0xffffffffu, m1, o));
        m2 = fmaxf(m2, __shfl_xor_sync(0xffffffffu, m2, o));
    }
    if (lane == 0) { red[0][wrp] = m1; red[1][wrp] = m2; }
    __syncthreads();
    m1 = fmaxf(fmaxf(red[0][0], red[0][1]), fmaxf(red[0][2], red[0][3]));
    m2 = fmaxf(fmaxf(red[1][0], red[1][1]), fmaxf(red[1][2], red[1][3]));
    __syncthreads();

    // block sum of exps per branch
    float e1[4], e2[4], s1 = 0.f, s2 = 0.f;
    #pragma unroll
    for (int i = 0; i < 4; i++) {
        e1[i] = __expf(v1[i] - m1);  s1 += e1[i];
        e2[i] = __expf(v2[i] - m2);  s2 += e2[i];
    }
    #pragma unroll
    for (int o = 16; o > 0; o >>= 1) {
        s1 += __shfl_xor_sync(0xffffffffu, s1, o);
        s2 += __shfl_xor_sync(0xffffffffu, s2, o);
    }
    if (lane == 0) { red[0][wrp] = s1; red[1][wrp] = s2; }
    __syncthreads();
    s1 = red[0][0] + red[0][1] + red[0][2] + red[0][3];
    s2 = red[1][0] + red[1][1] + red[1][2] + red[1][3];

    // this block's weights: s-chunk sz covers s = sz*128 + tid -> chunk index sz
    ws[tid] = (e1[sz]/s1 + e2[sz]/s2) * (0.5f / (float)S_);
    __syncthreads();

    // weighted sum over this block's 128 s values (fp16 source)
    const int sbeg = sz * (S_/SSPLIT);
    const int t2 = blockIdx.x * 128 + tid;     // half2 index into T_/2 = 384
    float a0 = 0.f, a1 = 0.f;
    const __half2* p = (const __half2*)g_Ah
                     + ((size_t)sbeg * B_ + b) * (T_/2) + t2;
    #pragma unroll 8
    for (int s = 0; s < S_/SSPLIT; s++) {
        float2 x = __half22float2(p[(size_t)s * B_ * (T_/2)]);
        a0 = fmaf(ws[s], x.x, a0);
        a1 = fmaf(ws[s], x.y, a1);
    }
    atomicAdd(&out[b*T_ + t2*2],     a0);
    atomicAdd(&out[b*T_ + t2*2 + 1], a1);
}

// ---------------------------------------------------------------------------
extern "C" void kernel_launch(void* const* d_in, const int* in_sizes, int n_in,
                              void* d_out, int out_size) {
    const float* text = (const float*)d_in[0];
    const float* anp  = (const float*)d_in[1];
    const float* ts   = (const float*)d_in[2];
    const float* W11  = (const float*)d_in[3];
    const float* b11  = (const float*)d_in[4];
    const float* W21  = (const float*)d_in[5];
    // d_in[6] = b21 (softmax shift-invariant -> unused)
    const float* W12  = (const float*)d_in[7];
    const float* b12  = (const float*)d_in[8];
    const float* W22  = (const float*)d_in[9];
    // d_in[10] = b22 (unused)
    (void)in_sizes; (void)n_in; (void)out_size;

    cudaFuncSetAttribute(fused_score_mma,
                         cudaFuncAttributeMaxDynamicSharedMemorySize, SMEM_DYN);

    init_misc_kernel<<<B_*NTOT/256, 256>>>(b11, b12, W21, W22, (float*)d_out);

    mega_prep_kernel<<<MEGA_BLOCKS, 256>>>(text, anp, ts, W11, W12);

    dim3 g1(NTOT/BN, M_/BM);   // (11, 256), N-tiles fastest -> A reuse in L2
    fused_score_mma<<<g1, 256, SMEM_DYN>>>();

    dim3 g2(T_/2/128, B_, SSPLIT);   // (3, 64, 4)
    softmax_wsum_kernel<<<g2, 128>>>((float*)d_out);
}